// round 5
// baseline (speedup 1.0000x reference)
#include <cuda_runtime.h>
#include <math.h>

#define Tt 2
#define Nn 10000
#define Ee 30000
#define LN_EPS 1e-5f

typedef unsigned long long ull;

// ---------------- scratch ----------------
__device__ float g_V[(size_t)Nn * 256];   // V[n][a*64+i]
__device__ float g_P[(size_t)Nn * 256];   // P[n][a*64+i]:  U = I - P V^T
__device__ float g_hfused[Nn * 64];
__device__ float g_agg[Nn * 64];
__device__ float g_w[Nn * 64];            // w_n = U_n^T h_new[n]
__device__ float g_hcat[(size_t)Ee * 128];// per-edge [h_row | h_trans]
__device__ float g_W1T[64 * 128];         // W1T[o][k] = W1[k][o]
__device__ float g_W2T[64 * 64];
__device__ int   g_idx[Tt * 2 * Ee];
__device__ int   g_is64;

// ---------------- packed f32x2 helpers ----------------
__device__ __forceinline__ ull dup2(float x) {
    ull r; asm("mov.b64 %0, {%1, %1};" : "=l"(r) : "f"(x)); return r;
}
__device__ __forceinline__ void fma2(ull& acc, ull a, ull b) {
    asm("fma.rn.f32x2 %0, %1, %2, %0;" : "+l"(acc) : "l"(a), "l"(b));
}
__device__ __forceinline__ float2 unpk(ull v) {
    float2 r; asm("mov.b64 {%0, %1}, %2;" : "=f"(r.x), "=f"(r.y) : "l"(v)); return r;
}

// ---------------- index dtype detection + conversion ----------------
__global__ void detect_kernel(const int* p) {
    __shared__ int any;
    if (threadIdx.x == 0) any = 0;
    __syncthreads();
    for (int i = threadIdx.x; i < 500; i += blockDim.x)
        if (p[2 * i + 1] != 0) any = 1;
    __syncthreads();
    if (threadIdx.x == 0) g_is64 = (any == 0);
}

__global__ void convert_kernel(const void* src) {
    int i = blockIdx.x * blockDim.x + threadIdx.x;
    if (i >= Tt * 2 * Ee) return;
    if (g_is64) g_idx[i] = (int)((const long long*)src)[i];
    else        g_idx[i] = ((const int*)src)[i];
}

// ---------------- weight transpose (once) ----------------
__global__ void prep_weights(const float* __restrict__ W1, const float* __restrict__ W2) {
    int i = blockIdx.x * 256 + threadIdx.x;
    if (i < 64 * 128) { int o = i >> 7, k = i & 127; g_W1T[o * 128 + k] = W1[k * 64 + o]; }
    if (i < 64 * 64)  { int o = i >> 6, k = i & 63;  g_W2T[o * 64 + k]  = W2[k * 64 + o]; }
}

// ---------------- fuse ----------------
__global__ void fuse_kernel(const float* __restrict__ hseq_t,
                            const float* __restrict__ hprev) {
    int i = blockIdx.x * blockDim.x + threadIdx.x;
    if (i < Nn * 64) {
        g_hfused[i] = hprev[i] + hseq_t[i];
        g_agg[i] = 0.f;
    }
}

// ---------------- frames: 16 nodes/block, fW staged in smem ----------------
__global__ void __launch_bounds__(512) frames_kernel(const float* __restrict__ fW,
                                                     const float* __restrict__ fb) {
    extern __shared__ __align__(16) float smem[];
    float* sfW  = smem;                 // [64][256]
    float* sH   = sfW + 16384;          // [16][64]
    float* sV   = sH + 1024;            // [16][256]
    float* sdot = sV + 4096;            // [16][16]
    float* sT   = sdot + 256;           // [16][16]

    int tid = threadIdx.x;
    int nbase = blockIdx.x * 16;

    {
        const float4* s4 = (const float4*)fW;
        float4* d4 = (float4*)sfW;
#pragma unroll
        for (int i = 0; i < 8; i++) d4[tid + i * 512] = s4[tid + i * 512];
        sH[tid] = g_hfused[nbase * 64 + tid];
        sH[tid + 512] = g_hfused[nbase * 64 + tid + 512];
    }
    __syncthreads();

    int cg = tid & 63, np = tid >> 6;
    int c0 = cg * 4, n0 = np * 2;
    float acc0[4] = {0, 0, 0, 0}, acc1[4] = {0, 0, 0, 0};
    const float* h0 = &sH[n0 * 64];
    const float* h1 = &sH[(n0 + 1) * 64];
#pragma unroll 4
    for (int k = 0; k < 64; k += 4) {
        float4 ha = *(const float4*)&h0[k];
        float4 hb = *(const float4*)&h1[k];
        float va[4] = {ha.x, ha.y, ha.z, ha.w};
        float vb[4] = {hb.x, hb.y, hb.z, hb.w};
#pragma unroll
        for (int kk = 0; kk < 4; kk++) {
            float4 w = *(const float4*)&sfW[(k + kk) * 256 + c0];
            acc0[0] += va[kk] * w.x; acc0[1] += va[kk] * w.y;
            acc0[2] += va[kk] * w.z; acc0[3] += va[kk] * w.w;
            acc1[0] += vb[kk] * w.x; acc1[1] += vb[kk] * w.y;
            acc1[2] += vb[kk] * w.z; acc1[3] += vb[kk] * w.w;
        }
    }
    {
        float4 fbv = *(const float4*)&fb[c0];
        acc0[0] += fbv.x; acc0[1] += fbv.y; acc0[2] += fbv.z; acc0[3] += fbv.w;
        acc1[0] += fbv.x; acc1[1] += fbv.y; acc1[2] += fbv.z; acc1[3] += fbv.w;
    }
    float ss0 = acc0[0]*acc0[0]+acc0[1]*acc0[1]+acc0[2]*acc0[2]+acc0[3]*acc0[3];
    float ss1 = acc1[0]*acc1[0]+acc1[1]*acc1[1]+acc1[2]*acc1[2]+acc1[3]*acc1[3];
#pragma unroll
    for (int m = 1; m < 16; m <<= 1) {
        ss0 += __shfl_xor_sync(0xffffffffu, ss0, m);
        ss1 += __shfl_xor_sync(0xffffffffu, ss1, m);
    }
    float rn0 = 1.f / (sqrtf(ss0) + 1e-8f);
    float rn1 = 1.f / (sqrtf(ss1) + 1e-8f);
#pragma unroll
    for (int cc = 0; cc < 4; cc++) {
        sV[n0 * 256 + c0 + cc] = acc0[cc] * rn0;
        sV[(n0 + 1) * 256 + c0 + cc] = acc1[cc] * rn1;
    }
    __syncthreads();

    if (tid < 384) {
        int did = tid >> 2, l = tid & 3;
        int n = did / 6, p = did - n * 6;
        const int pj[6] = {1, 2, 2, 3, 3, 3}, pk[6] = {0, 0, 1, 0, 1, 2};
        const float* vj = &sV[n * 256 + pj[p] * 64];
        const float* vk = &sV[n * 256 + pk[p] * 64];
        float s = 0.f;
#pragma unroll 4
        for (int i = l; i < 64; i += 4) s += vj[i] * vk[i];
        s += __shfl_xor_sync(0xffffffffu, s, 1);
        s += __shfl_xor_sync(0xffffffffu, s, 2);
        if (l == 0) sdot[n * 16 + pj[p] * 4 + pk[p]] = s;
    }
    __syncthreads();

    if (tid < 16) {
        int n = tid;
        float Tl[4][4];
        for (int j = 0; j < 4; j++) {
            for (int i = 0; i < j; i++) {
                float z = 0.f;
                for (int k = i; k < j; k++) z += sdot[n * 16 + j * 4 + k] * Tl[k][i];
                Tl[j][i] = -2.f * z;
            }
            Tl[j][j] = 2.f;
            for (int i = j + 1; i < 4; i++) Tl[j][i] = 0.f;
        }
        for (int k = 0; k < 4; k++)
            for (int a = 0; a < 4; a++) sT[n * 16 + k * 4 + a] = Tl[k][a];
    }
    __syncthreads();

    int a = c0 >> 6;
#pragma unroll
    for (int idx = 0; idx < 2; idx++) {
        int nl = n0 + idx;
        int ng = nbase + nl;
        float pv[4];
#pragma unroll
        for (int cc = 0; cc < 4; cc++) {
            int i = (c0 & 63) + cc;
            float s = 0.f;
#pragma unroll
            for (int k = 0; k < 4; k++) s += sV[nl * 256 + k * 64 + i] * sT[nl * 16 + k * 4 + a];
            pv[cc] = s;
        }
        *(float4*)&g_P[(size_t)ng * 256 + c0] = make_float4(pv[0], pv[1], pv[2], pv[3]);
        *(float4*)&g_V[(size_t)ng * 256 + c0] = *(float4*)&sV[nl * 256 + c0];
    }
}

// ---------------- qgen: one 512-thread block per edge ----------------
// Q[i][j] = delta_ij + sum_{b<8} A[i][b]*B[b][j],
//   B = [Vr(4) | Pc(4)], A = [-Pr | Pr*G - Vc]
__global__ void __launch_bounds__(512) qgen_kernel(int t, float* __restrict__ Qout) {
    int e = blockIdx.x, tid = threadIdx.x;
    __shared__ __align__(16) float sB[512];    // [b][j]
    __shared__ __align__(16) float sVc[256];
    __shared__ __align__(16) float sPr[256];
    __shared__ __align__(16) float sA[64 * 8]; // A[i][b] row-major
    __shared__ float sHc[64], sHr[64];
    __shared__ float sG[16], sS[8];

    int row = g_idx[t * 2 * Ee + e];
    int col = g_idx[t * 2 * Ee + Ee + e];

    if (tid < 256) {
        sB[tid]        = g_V[(size_t)row * 256 + tid];  // Vr
        sPr[tid]       = g_P[(size_t)row * 256 + tid];
        sB[256 + tid]  = g_P[(size_t)col * 256 + tid];  // Pc
        sVc[tid]       = g_V[(size_t)col * 256 + tid];
    } else if (tid < 320) {
        sHc[tid - 256] = g_hfused[(size_t)col * 64 + (tid - 256)];
    } else if (tid < 384) {
        sHr[tid - 320] = g_hfused[(size_t)row * 64 + (tid - 320)];
    }
    __syncthreads();

    // 24 small dots, 16 lanes each (dots 0-15: G[a][b]; 16-23: S)
    if (tid < 384) {
        int dd = tid >> 4, l = tid & 15;
        const float *va, *vb;
        if (dd < 16) { va = &sB[(dd >> 2) * 64]; vb = &sVc[(dd & 3) * 64]; }
        else {
            int d2 = dd - 16;
            va = (d2 < 4) ? &sB[d2 * 64] : &sB[256 + (d2 - 4) * 64];
            vb = sHc;
        }
        float s = 0.f;
#pragma unroll
        for (int q = 0; q < 4; q++) s += va[l + 16 * q] * vb[l + 16 * q];
        s += __shfl_xor_sync(0xffffffffu, s, 8);
        s += __shfl_xor_sync(0xffffffffu, s, 4);
        s += __shfl_xor_sync(0xffffffffu, s, 2);
        s += __shfl_xor_sync(0xffffffffu, s, 1);
        if (l == 0) { if (dd < 16) sG[dd] = s; else sS[dd - 16] = s; }
    }
    __syncthreads();

    // A rows + h_trans (threads 0-63)
    if (tid < 64) {
        int i = tid;
        float pr[4], A8[8];
#pragma unroll
        for (int a = 0; a < 4; a++) { pr[a] = sPr[a * 64 + i]; A8[a] = -pr[a]; }
#pragma unroll
        for (int b = 0; b < 4; b++) {
            float s = 0.f;
#pragma unroll
            for (int a = 0; a < 4; a++) s += pr[a] * sG[a * 4 + b];
            A8[4 + b] = s - sVc[b * 64 + i];
        }
        float ht = sHc[i];
#pragma unroll
        for (int b = 0; b < 8; b++) { sA[i * 8 + b] = A8[b]; ht += A8[b] * sS[b]; }
        g_hcat[(size_t)e * 128 + i] = sHr[i];
        g_hcat[(size_t)e * 128 + 64 + i] = ht;
    }
    __syncthreads();

    // Q expansion: thread -> (row i, col block j0..j0+7)
    int i = tid >> 3, j0 = (tid & 7) * 8;
    float4 af0 = *(const float4*)&sA[i * 8];
    float4 af1 = *(const float4*)&sA[i * 8 + 4];
    float a8[8] = {af0.x, af0.y, af0.z, af0.w, af1.x, af1.y, af1.z, af1.w};
    ull acc0 = 0ULL, acc1 = 0ULL, acc2 = 0ULL, acc3 = 0ULL;
#pragma unroll
    for (int b = 0; b < 8; b++) {
        ull d = dup2(a8[b]);
        ulonglong2 u = *(const ulonglong2*)&sB[b * 64 + j0];
        ulonglong2 u2 = *(const ulonglong2*)&sB[b * 64 + j0 + 4];
        fma2(acc0, d, u.x);  fma2(acc1, d, u.y);
        fma2(acc2, d, u2.x); fma2(acc3, d, u2.y);
    }
    float2 u0 = unpk(acc0), u1 = unpk(acc1), u2 = unpk(acc2), u3 = unpk(acc3);
    float q[8] = {u0.x, u0.y, u1.x, u1.y, u2.x, u2.y, u3.x, u3.y};
    int dj = i - j0;
    if (dj >= 0 && dj < 8) q[dj] += 1.f;
    float* qb = Qout + (size_t)e * 4096 + i * 64 + j0;
    *(float4*)qb       = make_float4(q[0], q[1], q[2], q[3]);
    *(float4*)(qb + 4) = make_float4(q[4], q[5], q[6], q[7]);
}

// ---------------- mlp: persistent blocks, weights staged once ----------------
#define MLP_BLOCKS 250
#define MLP_ITERS  (Ee / (MLP_BLOCKS * 4))   // 30
#define MLP_SMEM   ((64 * 130 + 64 * 66 + 4 * 128 + 4 * 64) * 4)
__global__ void __launch_bounds__(256) mlp_kernel(int t,
                                                  const float* __restrict__ b1,
                                                  const float* __restrict__ b2) {
    extern __shared__ __align__(16) float sm[];
    float* sW1T  = sm;                        // [64][130]
    float* sW2T  = sm + 64 * 130;             // [64][66]
    float* sHcat = sW2T + 64 * 66;            // [4][128]
    float* sM1   = sHcat + 512;               // [4][64]

    int tid = threadIdx.x;
    for (int i = tid; i < 64 * 128; i += 256) {
        int o = i >> 7, k = i & 127;
        sW1T[o * 130 + k] = g_W1T[i];
    }
    for (int i = tid; i < 64 * 64; i += 256) {
        int o = i >> 6, k = i & 63;
        sW2T[o * 66 + k] = g_W2T[i];
    }
    int g = tid >> 6, et = tid & 63;
    float bb1 = b1[et], bb2 = b2[et];
    float* hc = &sHcat[g * 128];
    const float* w1 = &sW1T[et * 130];
    const float* w2 = &sW2T[et * 66];
    __syncthreads();

    for (int it = 0; it < MLP_ITERS; it++) {
        int e = (blockIdx.x + it * MLP_BLOCKS) * 4 + g;
        hc[et]      = g_hcat[(size_t)e * 128 + et];
        hc[64 + et] = g_hcat[(size_t)e * 128 + 64 + et];
        __syncthreads();
        ull acc = 0ULL;
#pragma unroll 16
        for (int k = 0; k < 128; k += 2)
            fma2(acc, *(const ull*)&hc[k], *(const ull*)&w1[k]);
        float2 u = unpk(acc);
        sM1[g * 64 + et] = fmaxf(u.x + u.y + bb1, 0.f);
        __syncthreads();
        ull acc2 = 0ULL;
#pragma unroll 16
        for (int k = 0; k < 64; k += 2)
            fma2(acc2, *(const ull*)&sM1[g * 64 + k], *(const ull*)&w2[k]);
        float2 v = unpk(acc2);
        int row = g_idx[t * 2 * Ee + e];
        atomicAdd(&g_agg[(size_t)row * 64 + et], v.x + v.y + bb2);
        __syncthreads();
    }
}

// ---------------- GRU + LN + w : 8 nodes/block, weights staged ----------------
#define GRU_SMEM ((12288 * 2 + 512 * 3 + 32) * 4)
__global__ void __launch_bounds__(512) gru_kernel(const float* __restrict__ Wx,
                                                  const float* __restrict__ Wh,
                                                  const float* __restrict__ gb,
                                                  const float* __restrict__ gamma,
                                                  const float* __restrict__ beta,
                                                  float* __restrict__ out_h,
                                                  float* __restrict__ out_last) {
    extern __shared__ __align__(16) float smem[];
    float* sWx = smem;
    float* sWh = sWx + 12288;
    float* sa  = sWh + 12288;
    float* shb = sa + 512;
    float* rs  = shb + 512;
    float* ssv = rs + 512;

    int tid = threadIdx.x;
    int nbase = blockIdx.x * 8;
    {
        const float4* wx4 = (const float4*)Wx;
        const float4* wh4 = (const float4*)Wh;
        float4* sx4 = (float4*)sWx;
        float4* sh4 = (float4*)sWh;
#pragma unroll
        for (int i = 0; i < 6; i++) {
            sx4[tid + i * 512] = wx4[tid + i * 512];
            sh4[tid + i * 512] = wh4[tid + i * 512];
        }
        sa[tid] = g_agg[nbase * 64 + tid];
        shb[tid] = g_hfused[nbase * 64 + tid];
    }
    __syncthreads();

    int ln = tid >> 6, tn = tid & 63;
    int n = nbase + ln;
    const float* san = &sa[ln * 64];
    const float* shn = &shb[ln * 64];
    float gxz = 0, gxr = 0, gxn = 0, ghz = 0, ghr = 0, ghn = 0;
#pragma unroll 4
    for (int d = 0; d < 64; d++) {
        float a = san[d], h = shn[d];
        const float* wx = &sWx[d * 192];
        const float* wh = &sWh[d * 192];
        gxz += a * wx[tn];        ghz += h * wh[tn];
        gxr += a * wx[64 + tn];   ghr += h * wh[64 + tn];
        gxn += a * wx[128 + tn];  ghn += h * wh[128 + tn];
    }
    float z  = 1.f / (1.f + expf(-(gxz + ghz + gb[tn])));
    float r  = 1.f / (1.f + expf(-(gxr + ghr + gb[64 + tn])));
    float nn = tanhf(gxn + r * ghn + gb[128 + tn]);
    float hn = (1.f - z) * nn + z * shn[tn];

    float* rsn = &rs[ln * 64];
    rsn[tn] = hn;
    __syncthreads();
    for (int s = 32; s > 0; s >>= 1) {
        if (tn < s) rsn[tn] += rsn[tn + s];
        __syncthreads();
    }
    float mu = rsn[0] * (1.f / 64.f);
    __syncthreads();
    float dctr = hn - mu;
    rsn[tn] = dctr * dctr;
    __syncthreads();
    for (int s = 32; s > 0; s >>= 1) {
        if (tn < s) rsn[tn] += rsn[tn + s];
        __syncthreads();
    }
    float var = rsn[0] * (1.f / 64.f);
    float o = dctr * rsqrtf(var + LN_EPS) * gamma[tn] + beta[tn];
    out_h[(size_t)n * 64 + tn] = o;
    if (out_last) out_last[(size_t)n * 64 + tn] = o;

    __syncthreads();
    rsn[tn] = o;
    __syncthreads();
    const float* gV = g_V + (size_t)n * 256;
    const float* gP = g_P + (size_t)n * 256;
    if (tn < 4) {
        float s = 0.f;
        for (int i = 0; i < 64; i++) s += gP[tn * 64 + i] * rsn[i];
        ssv[ln * 4 + tn] = s;
    }
    __syncthreads();
    float w = o;
#pragma unroll
    for (int a = 0; a < 4; a++) w -= gV[a * 64 + tn] * ssv[ln * 4 + a];
    g_w[(size_t)n * 64 + tn] = w;
}

// ---------------- dis = ||w_row - w_col||^2 ----------------
__global__ void __launch_bounds__(256) dis_kernel(int t, float* __restrict__ dout) {
    int grp = threadIdx.x >> 6;
    int tid = threadIdx.x & 63;
    int e = blockIdx.x * 4 + grp;
    __shared__ float red[256];
    float v = 0.f;
    if (e < Ee) {
        int row = g_idx[t * 2 * Ee + e];
        int col = g_idx[t * 2 * Ee + Ee + e];
        float d = g_w[row * 64 + tid] - g_w[col * 64 + tid];
        v = d * d;
    }
    red[threadIdx.x] = v;
    __syncthreads();
    for (int s = 32; s > 0; s >>= 1) {
        if (tid < s) red[threadIdx.x] += red[threadIdx.x + s];
        __syncthreads();
    }
    if (tid == 0 && e < Ee) dout[e] = red[grp * 64];
}

// ---------------- launch ----------------
extern "C" void kernel_launch(void* const* d_in, const int* in_sizes, int n_in,
                              void* d_out, int out_size) {
    const float* hseq = (const float*)d_in[0];
    const void*  ei   = d_in[1];
    const float* fW   = (const float*)d_in[2];
    const float* fb   = (const float*)d_in[3];
    const float* W1   = (const float*)d_in[4];
    const float* b1   = (const float*)d_in[5];
    const float* W2   = (const float*)d_in[6];
    const float* b2   = (const float*)d_in[7];
    const float* Wx   = (const float*)d_in[8];
    const float* Wh   = (const float*)d_in[9];
    const float* gb   = (const float*)d_in[10];
    const float* gamma = (const float*)d_in[11];
    const float* beta  = (const float*)d_in[12];

    float* out = (float*)d_out;
    float* out_hlast = out;
    float* out_allh  = out + (size_t)Nn * 64;
    float* out_alld  = out_allh + (size_t)Tt * Nn * 64;
    float* out_allq  = out_alld + (size_t)Tt * Ee;

    const int frames_smem = 22016 * 4;
    cudaFuncSetAttribute(frames_kernel, cudaFuncAttributeMaxDynamicSharedMemorySize, frames_smem);
    cudaFuncSetAttribute(mlp_kernel,    cudaFuncAttributeMaxDynamicSharedMemorySize, MLP_SMEM);
    cudaFuncSetAttribute(gru_kernel,    cudaFuncAttributeMaxDynamicSharedMemorySize, GRU_SMEM);

    detect_kernel<<<1, 256>>>((const int*)ei);
    convert_kernel<<<(Tt * 2 * Ee + 255) / 256, 256>>>(ei);
    prep_weights<<<32, 256>>>(W1, W2);

    for (int t = 0; t < Tt; t++) {
        const float* hprev = (t == 0) ? hseq : (out_allh + (size_t)(t - 1) * Nn * 64);
        fuse_kernel<<<(Nn * 64 + 255) / 256, 256>>>(hseq + (size_t)t * Nn * 64, hprev);
        frames_kernel<<<Nn / 16, 512, frames_smem>>>(fW, fb);
        qgen_kernel<<<Ee, 512>>>(t, out_allq + (size_t)t * Ee * 4096);
        mlp_kernel<<<MLP_BLOCKS, 256, MLP_SMEM>>>(t, b1, b2);
        gru_kernel<<<Nn / 8, 512, GRU_SMEM>>>(Wx, Wh, gb, gamma, beta,
                                              out_allh + (size_t)t * Nn * 64,
                                              (t == Tt - 1) ? out_hlast : nullptr);
        dis_kernel<<<(Ee + 3) / 4, 256>>>(t, out_alld + (size_t)t * Ee);
    }
}

// round 6
// speedup vs baseline: 1.9429x; 1.9429x over previous
#include <cuda_runtime.h>
#include <math.h>

#define Tt 2
#define Nn 10000
#define Ee 30000
#define LN_EPS 1e-5f

typedef unsigned long long ull;

// ---------------- scratch ----------------
__device__ float g_V[(size_t)Nn * 256];   // V[n][a*64+i]
__device__ float g_P[(size_t)Nn * 256];   // P[n][a*64+i]:  U = I - P V^T
__device__ float g_hfused[Nn * 64];
__device__ float g_agg[Nn * 64];
__device__ float g_w[Nn * 64];            // w_n = U_n^T h_new[n]
__device__ float g_W1T[64 * 128];         // W1T[o][k] = W1[k][o]
__device__ float g_W2T[64 * 64];
__device__ int   g_idx[Tt * 2 * Ee];
__device__ int   g_is64;

// ---------------- packed f32x2 helpers ----------------
__device__ __forceinline__ ull dup2(float x) {
    ull r; asm("mov.b64 %0, {%1, %1};" : "=l"(r) : "f"(x)); return r;
}
__device__ __forceinline__ ull pk2(float a, float b) {
    ull r; asm("mov.b64 %0, {%1, %2};" : "=l"(r) : "f"(a), "f"(b)); return r;
}
__device__ __forceinline__ void fma2(ull& acc, ull a, ull b) {
    asm("fma.rn.f32x2 %0, %1, %2, %0;" : "+l"(acc) : "l"(a), "l"(b));
}
__device__ __forceinline__ float2 unpk(ull v) {
    float2 r; asm("mov.b64 {%0, %1}, %2;" : "=f"(r.x), "=f"(r.y) : "l"(v)); return r;
}
#define BARG(id) asm volatile("bar.sync %0, 64;" :: "r"(id) : "memory")

// ---------------- index dtype detection + conversion ----------------
__global__ void detect_kernel(const int* p) {
    __shared__ int any;
    if (threadIdx.x == 0) any = 0;
    __syncthreads();
    for (int i = threadIdx.x; i < 500; i += blockDim.x)
        if (p[2 * i + 1] != 0) any = 1;
    __syncthreads();
    if (threadIdx.x == 0) g_is64 = (any == 0);
}

__global__ void convert_kernel(const void* src) {
    int i = blockIdx.x * blockDim.x + threadIdx.x;
    if (i >= Tt * 2 * Ee) return;
    if (g_is64) g_idx[i] = (int)((const long long*)src)[i];
    else        g_idx[i] = ((const int*)src)[i];
}

// ---------------- weight transpose (once) ----------------
__global__ void prep_weights(const float* __restrict__ W1, const float* __restrict__ W2) {
    int i = blockIdx.x * 256 + threadIdx.x;
    if (i < 64 * 128) { int o = i >> 7, k = i & 127; g_W1T[o * 128 + k] = W1[k * 64 + o]; }
    if (i < 64 * 64)  { int o = i >> 6, k = i & 63;  g_W2T[o * 64 + k]  = W2[k * 64 + o]; }
}

// ---------------- fuse ----------------
__global__ void fuse_kernel(const float* __restrict__ hseq_t,
                            const float* __restrict__ hprev) {
    int i = blockIdx.x * blockDim.x + threadIdx.x;
    if (i < Nn * 64) {
        g_hfused[i] = hprev[i] + hseq_t[i];
        g_agg[i] = 0.f;
    }
}

// ---------------- frames: 16 nodes/block, fW staged in smem ----------------
__global__ void __launch_bounds__(512) frames_kernel(const float* __restrict__ fW,
                                                     const float* __restrict__ fb) {
    extern __shared__ __align__(16) float smem[];
    float* sfW  = smem;                 // [64][256]
    float* sH   = sfW + 16384;          // [16][64]
    float* sV   = sH + 1024;            // [16][256]
    float* sdot = sV + 4096;            // [16][16]
    float* sT   = sdot + 256;           // [16][16]

    int tid = threadIdx.x;
    int nbase = blockIdx.x * 16;

    {
        const float4* s4 = (const float4*)fW;
        float4* d4 = (float4*)sfW;
#pragma unroll
        for (int i = 0; i < 8; i++) d4[tid + i * 512] = s4[tid + i * 512];
        sH[tid] = g_hfused[nbase * 64 + tid];
        sH[tid + 512] = g_hfused[nbase * 64 + tid + 512];
    }
    __syncthreads();

    int cg = tid & 63, np = tid >> 6;
    int c0 = cg * 4, n0 = np * 2;
    float acc0[4] = {0, 0, 0, 0}, acc1[4] = {0, 0, 0, 0};
    const float* h0 = &sH[n0 * 64];
    const float* h1 = &sH[(n0 + 1) * 64];
#pragma unroll 4
    for (int k = 0; k < 64; k += 4) {
        float4 ha = *(const float4*)&h0[k];
        float4 hb = *(const float4*)&h1[k];
        float va[4] = {ha.x, ha.y, ha.z, ha.w};
        float vb[4] = {hb.x, hb.y, hb.z, hb.w};
#pragma unroll
        for (int kk = 0; kk < 4; kk++) {
            float4 w = *(const float4*)&sfW[(k + kk) * 256 + c0];
            acc0[0] += va[kk] * w.x; acc0[1] += va[kk] * w.y;
            acc0[2] += va[kk] * w.z; acc0[3] += va[kk] * w.w;
            acc1[0] += vb[kk] * w.x; acc1[1] += vb[kk] * w.y;
            acc1[2] += vb[kk] * w.z; acc1[3] += vb[kk] * w.w;
        }
    }
    {
        float4 fbv = *(const float4*)&fb[c0];
        acc0[0] += fbv.x; acc0[1] += fbv.y; acc0[2] += fbv.z; acc0[3] += fbv.w;
        acc1[0] += fbv.x; acc1[1] += fbv.y; acc1[2] += fbv.z; acc1[3] += fbv.w;
    }
    float ss0 = acc0[0]*acc0[0]+acc0[1]*acc0[1]+acc0[2]*acc0[2]+acc0[3]*acc0[3];
    float ss1 = acc1[0]*acc1[0]+acc1[1]*acc1[1]+acc1[2]*acc1[2]+acc1[3]*acc1[3];
#pragma unroll
    for (int m = 1; m < 16; m <<= 1) {
        ss0 += __shfl_xor_sync(0xffffffffu, ss0, m);
        ss1 += __shfl_xor_sync(0xffffffffu, ss1, m);
    }
    float rn0 = 1.f / (sqrtf(ss0) + 1e-8f);
    float rn1 = 1.f / (sqrtf(ss1) + 1e-8f);
#pragma unroll
    for (int cc = 0; cc < 4; cc++) {
        sV[n0 * 256 + c0 + cc] = acc0[cc] * rn0;
        sV[(n0 + 1) * 256 + c0 + cc] = acc1[cc] * rn1;
    }
    __syncthreads();

    if (tid < 384) {
        int did = tid >> 2, l = tid & 3;
        int n = did / 6, p = did - n * 6;
        const int pj[6] = {1, 2, 2, 3, 3, 3}, pk[6] = {0, 0, 1, 0, 1, 2};
        const float* vj = &sV[n * 256 + pj[p] * 64];
        const float* vk = &sV[n * 256 + pk[p] * 64];
        float s = 0.f;
#pragma unroll 4
        for (int i = l; i < 64; i += 4) s += vj[i] * vk[i];
        s += __shfl_xor_sync(0xffffffffu, s, 1);
        s += __shfl_xor_sync(0xffffffffu, s, 2);
        if (l == 0) sdot[n * 16 + pj[p] * 4 + pk[p]] = s;
    }
    __syncthreads();

    if (tid < 16) {
        int n = tid;
        float Tl[4][4];
        for (int j = 0; j < 4; j++) {
            for (int i = 0; i < j; i++) {
                float z = 0.f;
                for (int k = i; k < j; k++) z += sdot[n * 16 + j * 4 + k] * Tl[k][i];
                Tl[j][i] = -2.f * z;
            }
            Tl[j][j] = 2.f;
            for (int i = j + 1; i < 4; i++) Tl[j][i] = 0.f;
        }
        for (int k = 0; k < 4; k++)
            for (int a = 0; a < 4; a++) sT[n * 16 + k * 4 + a] = Tl[k][a];
    }
    __syncthreads();

    int a = c0 >> 6;
#pragma unroll
    for (int idx = 0; idx < 2; idx++) {
        int nl = n0 + idx;
        int ng = nbase + nl;
        float pv[4];
#pragma unroll
        for (int cc = 0; cc < 4; cc++) {
            int i = (c0 & 63) + cc;
            float s = 0.f;
#pragma unroll
            for (int k = 0; k < 4; k++) s += sV[nl * 256 + k * 64 + i] * sT[nl * 16 + k * 4 + a];
            pv[cc] = s;
        }
        *(float4*)&g_P[(size_t)ng * 256 + c0] = make_float4(pv[0], pv[1], pv[2], pv[3]);
        *(float4*)&g_V[(size_t)ng * 256 + c0] = *(float4*)&sV[nl * 256 + c0];
    }
}

// ---------------- persistent fused edge kernel ----------------
// 4 edges per block-iteration (one per 64-thread group, named barriers),
// W1T/W2T staged ONCE per block, grid-stride over 7500 edge groups.
#define EGRP (Ee / 4)
#define EDGE_BLOCKS 444
#define EDGE_SMEM ((64 * 130 + 64 * 66 + 4 * 1568) * 4)
__global__ void __launch_bounds__(256) edge_kernel(int t,
                                                   const float* __restrict__ b1,
                                                   const float* __restrict__ b2,
                                                   float* __restrict__ Qout) {
    extern __shared__ __align__(16) float sm[];
    float* sW1T = sm;                     // [64][130]
    float* sW2T = sm + 64 * 130;          // [64][66]
    float* sE   = sW2T + 64 * 66;

    int tid = threadIdx.x;
    for (int i = tid; i < 64 * 128; i += 256) {
        int o = i >> 7, k = i & 127;
        sW1T[o * 130 + k] = g_W1T[i];
    }
    for (int i = tid; i < 64 * 64; i += 256) {
        int o = i >> 6, k = i & 63;
        sW2T[o * 66 + k] = g_W2T[i];
    }

    int g = tid >> 6, et = tid & 63;
    int bid = g + 1;                      // named barrier id 1..4
    float* eb = sE + g * 1568;
    float4* sPr4 = (float4*)eb;           // [64] float4
    float4* sX4  = (float4*)(eb + 256);   // [64] float4
    float* sVr   = eb + 512;              // [4][64]
    float* sVc   = eb + 768;
    float* sPc   = eb + 1024;
    float* sHcat = eb + 1280;             // [128]
    float* sHc   = eb + 1408;             // [64]
    float* sM1   = eb + 1472;             // [64]
    float* sG    = eb + 1536;             // [16]
    float* sS    = eb + 1552;             // [8]
    const float* w1 = &sW1T[et * 130];
    const float* w2 = &sW2T[et * 66];
    float bb1 = b1[et], bb2 = b2[et];
    __syncthreads();

    for (int grp = blockIdx.x; grp < EGRP; grp += gridDim.x) {
        int e = grp * 4 + g;
        int row = g_idx[t * 2 * Ee + e];
        int col = g_idx[t * 2 * Ee + Ee + e];
        float pr[4];
#pragma unroll
        for (int a = 0; a < 4; a++) {
            sVr[a * 64 + et] = g_V[(size_t)row * 256 + a * 64 + et];
            sVc[a * 64 + et] = g_V[(size_t)col * 256 + a * 64 + et];
            sPc[a * 64 + et] = g_P[(size_t)col * 256 + a * 64 + et];
            pr[a] = g_P[(size_t)row * 256 + a * 64 + et];
        }
        sPr4[et] = make_float4(pr[0], pr[1], pr[2], pr[3]);
        sHcat[et] = g_hfused[(size_t)row * 64 + et];
        sHc[et] = g_hfused[(size_t)col * 64 + et];
        BARG(bid);

        // G dots: 16 dots x 4 lanes (G[a][b] = Vr_a . Vc_b)
        {
            int d = et >> 2, l = et & 3;
            const float* va = &sVr[(d >> 2) * 64];
            const float* vb = &sVc[(d & 3) * 64];
            float s = 0.f;
#pragma unroll
            for (int q = 0; q < 16; q++) s += va[l + 4 * q] * vb[l + 4 * q];
            s += __shfl_xor_sync(0xffffffffu, s, 1);
            s += __shfl_xor_sync(0xffffffffu, s, 2);
            if (l == 0) sG[d] = s;
        }
        // S dots: 8 dots x 8 lanes (S[0..3]=Vr.hc, S[4..7]=Pc.hc)
        {
            int d = et >> 3, l = et & 7;
            const float* va = (d < 4) ? &sVr[d * 64] : &sPc[(d - 4) * 64];
            float s = 0.f;
#pragma unroll
            for (int q = 0; q < 8; q++) s += va[l + 8 * q] * sHc[l + 8 * q];
            s += __shfl_xor_sync(0xffffffffu, s, 1);
            s += __shfl_xor_sync(0xffffffffu, s, 2);
            s += __shfl_xor_sync(0xffffffffu, s, 4);
            if (l == 0) sS[d] = s;
        }
        BARG(bid);

        // X rows + h_trans (all 64 threads, i = et)
        {
            float x[4];
#pragma unroll
            for (int b = 0; b < 4; b++) {
                float s = 0.f;
#pragma unroll
                for (int a = 0; a < 4; a++) s += pr[a] * sG[a * 4 + b];
                x[b] = s - sVc[b * 64 + et];
            }
            sX4[et] = make_float4(x[0], x[1], x[2], x[3]);
            float ht = sHc[et];
#pragma unroll
            for (int a = 0; a < 4; a++) ht += -pr[a] * sS[a] + x[a] * sS[4 + a];
            sHcat[64 + et] = ht;
        }
        BARG(bid);

        // Q expansion: thread -> (4 cols j0..j0+3, 16 rows)
        {
            int j0 = (et & 15) * 4, ig = et >> 4;
            ull vrn[4][2], pcp[4][2];
#pragma unroll
            for (int a = 0; a < 4; a++) {
                vrn[a][0] = pk2(-sVr[a * 64 + j0],     -sVr[a * 64 + j0 + 1]);
                vrn[a][1] = pk2(-sVr[a * 64 + j0 + 2], -sVr[a * 64 + j0 + 3]);
                pcp[a][0] = pk2(sPc[a * 64 + j0],      sPc[a * 64 + j0 + 1]);
                pcp[a][1] = pk2(sPc[a * 64 + j0 + 2],  sPc[a * 64 + j0 + 3]);
            }
            float* qbase = Qout + (size_t)e * 4096;
#pragma unroll 4
            for (int r = 0; r < 16; r++) {
                int i = ig * 16 + r;
                float4 prf = sPr4[i];
                float4 xf = sX4[i];
                ull q0 = 0ULL, q1 = 0ULL, d;
                d = dup2(prf.x); fma2(q0, d, vrn[0][0]); fma2(q1, d, vrn[0][1]);
                d = dup2(prf.y); fma2(q0, d, vrn[1][0]); fma2(q1, d, vrn[1][1]);
                d = dup2(prf.z); fma2(q0, d, vrn[2][0]); fma2(q1, d, vrn[2][1]);
                d = dup2(prf.w); fma2(q0, d, vrn[3][0]); fma2(q1, d, vrn[3][1]);
                d = dup2(xf.x);  fma2(q0, d, pcp[0][0]); fma2(q1, d, pcp[0][1]);
                d = dup2(xf.y);  fma2(q0, d, pcp[1][0]); fma2(q1, d, pcp[1][1]);
                d = dup2(xf.z);  fma2(q0, d, pcp[2][0]); fma2(q1, d, pcp[2][1]);
                d = dup2(xf.w);  fma2(q0, d, pcp[3][0]); fma2(q1, d, pcp[3][1]);
                float2 u0 = unpk(q0), u1 = unpk(q1);
                float q[4] = {u0.x, u0.y, u1.x, u1.y};
                int dj = i - j0;
                if (dj >= 0 && dj < 4) q[dj] += 1.f;
                *(float4*)&qbase[i * 64 + j0] = make_float4(q[0], q[1], q[2], q[3]);
            }
        }

        // MLP layer 1 (needs full sHcat; already synced above)
        {
            ull acc = 0ULL;
#pragma unroll 16
            for (int k = 0; k < 128; k += 2)
                fma2(acc, *(const ull*)&sHcat[k], *(const ull*)&w1[k]);
            float2 u = unpk(acc);
            sM1[et] = fmaxf(u.x + u.y + bb1, 0.f);
        }
        BARG(bid);
        // MLP layer 2 + scatter
        {
            ull acc = 0ULL;
#pragma unroll 16
            for (int k = 0; k < 64; k += 2)
                fma2(acc, *(const ull*)&sM1[k], *(const ull*)&w2[k]);
            float2 v = unpk(acc);
            atomicAdd(&g_agg[(size_t)row * 64 + et], v.x + v.y + bb2);
        }
        BARG(bid);  // all reads of region done before next iteration overwrites
    }
}

// ---------------- GRU + LN + w : 8 nodes/block, weights staged ----------------
#define GRU_SMEM ((12288 * 2 + 512 * 3 + 32) * 4)
__global__ void __launch_bounds__(512) gru_kernel(const float* __restrict__ Wx,
                                                  const float* __restrict__ Wh,
                                                  const float* __restrict__ gb,
                                                  const float* __restrict__ gamma,
                                                  const float* __restrict__ beta,
                                                  float* __restrict__ out_h,
                                                  float* __restrict__ out_last) {
    extern __shared__ __align__(16) float smem[];
    float* sWx = smem;
    float* sWh = sWx + 12288;
    float* sa  = sWh + 12288;
    float* shb = sa + 512;
    float* rs  = shb + 512;
    float* ssv = rs + 512;

    int tid = threadIdx.x;
    int nbase = blockIdx.x * 8;
    {
        const float4* wx4 = (const float4*)Wx;
        const float4* wh4 = (const float4*)Wh;
        float4* sx4 = (float4*)sWx;
        float4* sh4 = (float4*)sWh;
#pragma unroll
        for (int i = 0; i < 6; i++) {
            sx4[tid + i * 512] = wx4[tid + i * 512];
            sh4[tid + i * 512] = wh4[tid + i * 512];
        }
        sa[tid] = g_agg[nbase * 64 + tid];
        shb[tid] = g_hfused[nbase * 64 + tid];
    }
    __syncthreads();

    int ln = tid >> 6, tn = tid & 63;
    int n = nbase + ln;
    const float* san = &sa[ln * 64];
    const float* shn = &shb[ln * 64];
    float gxz = 0, gxr = 0, gxn = 0, ghz = 0, ghr = 0, ghn = 0;
#pragma unroll 4
    for (int d = 0; d < 64; d++) {
        float a = san[d], h = shn[d];
        const float* wx = &sWx[d * 192];
        const float* wh = &sWh[d * 192];
        gxz += a * wx[tn];        ghz += h * wh[tn];
        gxr += a * wx[64 + tn];   ghr += h * wh[64 + tn];
        gxn += a * wx[128 + tn];  ghn += h * wh[128 + tn];
    }
    float z  = 1.f / (1.f + expf(-(gxz + ghz + gb[tn])));
    float r  = 1.f / (1.f + expf(-(gxr + ghr + gb[64 + tn])));
    float nn = tanhf(gxn + r * ghn + gb[128 + tn]);
    float hn = (1.f - z) * nn + z * shn[tn];

    float* rsn = &rs[ln * 64];
    rsn[tn] = hn;
    __syncthreads();
    for (int s = 32; s > 0; s >>= 1) {
        if (tn < s) rsn[tn] += rsn[tn + s];
        __syncthreads();
    }
    float mu = rsn[0] * (1.f / 64.f);
    __syncthreads();
    float dctr = hn - mu;
    rsn[tn] = dctr * dctr;
    __syncthreads();
    for (int s = 32; s > 0; s >>= 1) {
        if (tn < s) rsn[tn] += rsn[tn + s];
        __syncthreads();
    }
    float var = rsn[0] * (1.f / 64.f);
    float o = dctr * rsqrtf(var + LN_EPS) * gamma[tn] + beta[tn];
    out_h[(size_t)n * 64 + tn] = o;
    if (out_last) out_last[(size_t)n * 64 + tn] = o;

    __syncthreads();
    rsn[tn] = o;
    __syncthreads();
    const float* gV = g_V + (size_t)n * 256;
    const float* gP = g_P + (size_t)n * 256;
    if (tn < 4) {
        float s = 0.f;
        for (int i = 0; i < 64; i++) s += gP[tn * 64 + i] * rsn[i];
        ssv[ln * 4 + tn] = s;
    }
    __syncthreads();
    float w = o;
#pragma unroll
    for (int a = 0; a < 4; a++) w -= gV[a * 64 + tn] * ssv[ln * 4 + a];
    g_w[(size_t)n * 64 + tn] = w;
}

// ---------------- dis = ||w_row - w_col||^2 ----------------
__global__ void __launch_bounds__(256) dis_kernel(int t, float* __restrict__ dout) {
    int grp = threadIdx.x >> 6;
    int tid = threadIdx.x & 63;
    int e = blockIdx.x * 4 + grp;
    __shared__ float red[256];
    float v = 0.f;
    if (e < Ee) {
        int row = g_idx[t * 2 * Ee + e];
        int col = g_idx[t * 2 * Ee + Ee + e];
        float d = g_w[row * 64 + tid] - g_w[col * 64 + tid];
        v = d * d;
    }
    red[threadIdx.x] = v;
    __syncthreads();
    for (int s = 32; s > 0; s >>= 1) {
        if (tid < s) red[threadIdx.x] += red[threadIdx.x + s];
        __syncthreads();
    }
    if (tid == 0 && e < Ee) dout[e] = red[grp * 64];
}

// ---------------- launch ----------------
extern "C" void kernel_launch(void* const* d_in, const int* in_sizes, int n_in,
                              void* d_out, int out_size) {
    const float* hseq = (const float*)d_in[0];
    const void*  ei   = d_in[1];
    const float* fW   = (const float*)d_in[2];
    const float* fb   = (const float*)d_in[3];
    const float* W1   = (const float*)d_in[4];
    const float* b1   = (const float*)d_in[5];
    const float* W2   = (const float*)d_in[6];
    const float* b2   = (const float*)d_in[7];
    const float* Wx   = (const float*)d_in[8];
    const float* Wh   = (const float*)d_in[9];
    const float* gb   = (const float*)d_in[10];
    const float* gamma = (const float*)d_in[11];
    const float* beta  = (const float*)d_in[12];

    float* out = (float*)d_out;
    float* out_hlast = out;
    float* out_allh  = out + (size_t)Nn * 64;
    float* out_alld  = out_allh + (size_t)Tt * Nn * 64;
    float* out_allq  = out_alld + (size_t)Tt * Ee;

    const int frames_smem = 22016 * 4;
    cudaFuncSetAttribute(frames_kernel, cudaFuncAttributeMaxDynamicSharedMemorySize, frames_smem);
    cudaFuncSetAttribute(edge_kernel,   cudaFuncAttributeMaxDynamicSharedMemorySize, EDGE_SMEM);
    cudaFuncSetAttribute(gru_kernel,    cudaFuncAttributeMaxDynamicSharedMemorySize, GRU_SMEM);

    detect_kernel<<<1, 256>>>((const int*)ei);
    convert_kernel<<<(Tt * 2 * Ee + 255) / 256, 256>>>(ei);
    prep_weights<<<32, 256>>>(W1, W2);

    for (int t = 0; t < Tt; t++) {
        const float* hprev = (t == 0) ? hseq : (out_allh + (size_t)(t - 1) * Nn * 64);
        fuse_kernel<<<(Nn * 64 + 255) / 256, 256>>>(hseq + (size_t)t * Nn * 64, hprev);
        frames_kernel<<<Nn / 16, 512, frames_smem>>>(fW, fb);
        edge_kernel<<<EDGE_BLOCKS, 256, EDGE_SMEM>>>(t, b1, b2,
                                                     out_allq + (size_t)t * Ee * 4096);
        gru_kernel<<<Nn / 8, 512, GRU_SMEM>>>(Wx, Wh, gb, gamma, beta,
                                              out_allh + (size_t)t * Nn * 64,
                                              (t == Tt - 1) ? out_hlast : nullptr);
        dis_kernel<<<(Ee + 3) / 4, 256>>>(t, out_alld + (size_t)t * Ee);
    }
}